// round 6
// baseline (speedup 1.0000x reference)
#include <cuda_runtime.h>

// HungarianMatcher cost matrix: C[bs,nq,nt] =
//   5*L1(cxcywh) + 2*focal_class_cost(gathered by tgt_id) - 2*GIoU(xyxy)
//
// R5 changes vs R4 (L1-ops + occupancy round):
//  - qd/td eliminated: w,h are qc.z,qc.w directly (cxcywh); areas via 1 hoisted
//    FMUL per iter + FADD per pair. Removes one LDS.128 per loop iteration and
//    ~8 target registers.
//  - __launch_bounds__(160,10): regs <= 40 => 10 CTAs/SM (50 warps, ~78% occ)
//    vs 8 CTAs (40 warps) before.

namespace {
constexpr int BS = 16, NQ = 900, NC = 91, NT = 1600;
constexpr int NROWS = BS * NQ;     // 14400
constexpr int TI = 10;             // query rows per block
constexpr int TPB = 160;           // 5 warps
constexpr int TGT_PER_BLK = 2 * TPB;       // 320
constexpr int NTILE_T = NT / TGT_PER_BLK;  // 5
}

__device__ float  g_cls2[NROWS * NC];   // 2*cost_class + 2
__device__ float4 g_qxyxy[NROWS];
__device__ float4 g_txyxy[NT];
__device__ float  g_tarea[NT];
__device__ int    g_tid[NT];

// Fused prep: class table (+2 fold) + box xyxy + target area + id decode.
// tgt_ids is int64 in the reference; jax with x64 disabled materializes
// int32. Detect: for nonneg int64 < 2^31, every odd int32 word is 0.
// All detection reads stay within the int32 buffer size.
__global__ void prep_all(const float* __restrict__ logits,
                         const float* __restrict__ pred_boxes,
                         const float* __restrict__ tgt_boxes,
                         const int*   __restrict__ ids32) {
    int i = blockIdx.x * blockDim.x + threadIdx.x;
    if (i < NROWS * NC) {
        float x = logits[i];
        float p = __fdividef(1.0f, 1.0f + __expf(-x));
        float omp = 1.0f - p;
        float pos = 0.25f * omp * omp * (-__logf(p + 1e-8f));
        float neg = 0.75f * p * p * (-__logf(omp + 1e-8f));
        g_cls2[i] = 2.0f * (pos - neg) + 2.0f;   // +2 from -2*giou's (-1) term
    }
    if (i < NROWS + NT) {
        if (i < NROWS) {
            float4 b = reinterpret_cast<const float4*>(pred_boxes)[i];
            float4 xy;
            xy.x = b.x - 0.5f * b.z; xy.y = b.y - 0.5f * b.w;
            xy.z = b.x + 0.5f * b.z; xy.w = b.y + 0.5f * b.w;
            g_qxyxy[i] = xy;
        } else {
            int j = i - NROWS;
            float4 b = reinterpret_cast<const float4*>(tgt_boxes)[j];
            float4 xy;
            xy.x = b.x - 0.5f * b.z; xy.y = b.y - 0.5f * b.w;
            xy.z = b.x + 0.5f * b.z; xy.w = b.y + 0.5f * b.w;
            g_txyxy[j] = xy;
            g_tarea[j] = b.z * b.w;
        }
    }
    if (i < NT) {
        bool is64 = true;
#pragma unroll
        for (int k = 1; k < 128; k += 2)
            is64 &= (ids32[k] == 0);
        g_tid[i] = is64 ? ids32[2 * i] : ids32[i];
    }
}

__device__ __forceinline__ float pair_cost(
    const float4 qxy, const float4 qc, const float qarea,
    const float4 txy, const float4 tc, const float tarea,
    const float cls2p)
{
    // L1 on cxcywh
    float bb = fabsf(qc.x - tc.x) + fabsf(qc.y - tc.y)
             + fabsf(qc.z - tc.z) + fabsf(qc.w - tc.w);
    // enclosing box; intersection derived from it:
    //   min(q2,t2) - max(q1,t1) = (qw + tw) - ex ; widths are qc.z/tc.z etc.
    float ex = fmaxf(qxy.z, txy.z) - fminf(qxy.x, txy.x);
    float ey = fmaxf(qxy.w, txy.w) - fminf(qxy.y, txy.y);
    float w  = fmaxf((qc.z + tc.z) - ex, 0.0f);
    float h  = fmaxf((qc.w + tc.w) - ey, 0.0f);
    float inter = w * h;
    float uni = (qarea + tarea) - inter;
    float ae  = ex * ey;
    // C = 5*bb + (2*cls+2) - 2*inter/uni - 2*uni/ae
    float c = fmaf(5.0f, bb, cls2p);
    c = fmaf(-2.0f * inter, __fdividef(1.0f, uni), c);
    c = fmaf(-2.0f * uni,   __fdividef(1.0f, ae),  c);
    return c;
}

__global__ void __launch_bounds__(TPB, 10)
cost_kernel(const float* __restrict__ pred_boxes,
            const float* __restrict__ tgt_boxes,
            float* __restrict__ out)
{
    __shared__ float  s_cls[TI * NC];   // 3.6 KB
    __shared__ float4 s_qxy[TI];
    __shared__ float4 s_qc[TI];

    const int t  = threadIdx.x;
    const int r0 = blockIdx.x * TI;
    const int j0 = blockIdx.y * TGT_PER_BLK + 2 * t;

    for (int k = t; k < TI * NC; k += TPB)
        s_cls[k] = g_cls2[r0 * NC + k];
    if (t < TI) {
        s_qxy[t] = g_qxyxy[r0 + t];
        s_qc[t]  = reinterpret_cast<const float4*>(pred_boxes)[r0 + t];
    }

    // per-thread target constants (registers)
    const float4 t0xy = g_txyxy[j0];
    const float4 t1xy = g_txyxy[j0 + 1];
    const float  t0a  = g_tarea[j0];
    const float  t1a  = g_tarea[j0 + 1];
    const float4 t0c  = reinterpret_cast<const float4*>(tgt_boxes)[j0];
    const float4 t1c  = reinterpret_cast<const float4*>(tgt_boxes)[j0 + 1];
    const int id0 = g_tid[j0];
    const int id1 = g_tid[j0 + 1];
    __syncthreads();

    float* orow = out + (size_t)r0 * NT + j0;

#pragma unroll
    for (int q = 0; q < TI; ++q) {
        const float4 qxy = s_qxy[q];
        const float4 qc  = s_qc[q];
        const float  qarea = qc.z * qc.w;        // hoisted once per q
        float c0 = pair_cost(qxy, qc, qarea, t0xy, t0c, t0a, s_cls[q * NC + id0]);
        float c1 = pair_cost(qxy, qc, qarea, t1xy, t1c, t1a, s_cls[q * NC + id1]);
        *reinterpret_cast<float2*>(orow + (size_t)q * NT) = make_float2(c0, c1);
    }
}

extern "C" void kernel_launch(void* const* d_in, const int* in_sizes, int n_in,
                              void* d_out, int out_size) {
    const float* logits = (const float*)d_in[0];   // [16,900,91]
    const float* pboxes = (const float*)d_in[1];   // [16,900,4]
    const float* tboxes = (const float*)d_in[2];   // [1600,4]
    const int*   ids    = (const int*)d_in[3];     // [1600] (int32 or int64 view)
    float* out = (float*)d_out;                    // [16,900,1600]

    prep_all<<<(NROWS * NC + 255) / 256, 256>>>(logits, pboxes, tboxes, ids);
    dim3 grid(NROWS / TI, NTILE_T);
    cost_kernel<<<grid, TPB>>>(pboxes, tboxes, out);
}

// round 7
// speedup vs baseline: 1.1056x; 1.1056x over previous
#include <cuda_runtime.h>

// HungarianMatcher cost matrix: C[bs,nq,nt] =
//   5*L1(cxcywh) + 2*focal_class_cost(gathered by tgt_id) - 2*GIoU(xyxy)
//
// R6 = R4 + R5's qd/td elimination, with minblocks=9 (reg cap 45) instead of
// R5's minblocks=10 (cap 32, which spilled the ~18 target-constant registers
// and regressed). Target constants must stay register-resident.

namespace {
constexpr int BS = 16, NQ = 900, NC = 91, NT = 1600;
constexpr int NROWS = BS * NQ;     // 14400
constexpr int TI = 10;             // query rows per block
constexpr int TPB = 160;           // 5 warps
constexpr int TGT_PER_BLK = 2 * TPB;       // 320
constexpr int NTILE_T = NT / TGT_PER_BLK;  // 5
}

__device__ float  g_cls2[NROWS * NC];   // 2*cost_class + 2
__device__ float4 g_qxyxy[NROWS];
__device__ float4 g_txyxy[NT];
__device__ float  g_tarea[NT];
__device__ int    g_tid[NT];

// Fused prep: class table (+2 fold) + box xyxy + target area + id decode.
// tgt_ids is int64 in the reference; jax with x64 disabled materializes
// int32. Detect: for nonneg int64 < 2^31, every odd int32 word is 0.
// All detection reads stay within the int32 buffer size.
__global__ void prep_all(const float* __restrict__ logits,
                         const float* __restrict__ pred_boxes,
                         const float* __restrict__ tgt_boxes,
                         const int*   __restrict__ ids32) {
    int i = blockIdx.x * blockDim.x + threadIdx.x;
    if (i < NROWS * NC) {
        float x = logits[i];
        float p = __fdividef(1.0f, 1.0f + __expf(-x));
        float omp = 1.0f - p;
        float pos = 0.25f * omp * omp * (-__logf(p + 1e-8f));
        float neg = 0.75f * p * p * (-__logf(omp + 1e-8f));
        g_cls2[i] = 2.0f * (pos - neg) + 2.0f;   // +2 from -2*giou's (-1) term
    }
    if (i < NROWS + NT) {
        if (i < NROWS) {
            float4 b = reinterpret_cast<const float4*>(pred_boxes)[i];
            float4 xy;
            xy.x = b.x - 0.5f * b.z; xy.y = b.y - 0.5f * b.w;
            xy.z = b.x + 0.5f * b.z; xy.w = b.y + 0.5f * b.w;
            g_qxyxy[i] = xy;
        } else {
            int j = i - NROWS;
            float4 b = reinterpret_cast<const float4*>(tgt_boxes)[j];
            float4 xy;
            xy.x = b.x - 0.5f * b.z; xy.y = b.y - 0.5f * b.w;
            xy.z = b.x + 0.5f * b.z; xy.w = b.y + 0.5f * b.w;
            g_txyxy[j] = xy;
            g_tarea[j] = b.z * b.w;
        }
    }
    if (i < NT) {
        bool is64 = true;
#pragma unroll
        for (int k = 1; k < 128; k += 2)
            is64 &= (ids32[k] == 0);
        g_tid[i] = is64 ? ids32[2 * i] : ids32[i];
    }
}

__device__ __forceinline__ float pair_cost(
    const float4 qxy, const float4 qc, const float qarea,
    const float4 txy, const float4 tc, const float tarea,
    const float cls2p)
{
    // L1 on cxcywh
    float bb = fabsf(qc.x - tc.x) + fabsf(qc.y - tc.y)
             + fabsf(qc.z - tc.z) + fabsf(qc.w - tc.w);
    // enclosing box; intersection derived from it:
    //   min(q2,t2) - max(q1,t1) = (qw + tw) - ex ; widths are qc.z/tc.z etc.
    float ex = fmaxf(qxy.z, txy.z) - fminf(qxy.x, txy.x);
    float ey = fmaxf(qxy.w, txy.w) - fminf(qxy.y, txy.y);
    float w  = fmaxf((qc.z + tc.z) - ex, 0.0f);
    float h  = fmaxf((qc.w + tc.w) - ey, 0.0f);
    float inter = w * h;
    float uni = (qarea + tarea) - inter;
    float ae  = ex * ey;
    // C = 5*bb + (2*cls+2) - 2*inter/uni - 2*uni/ae
    float c = fmaf(5.0f, bb, cls2p);
    c = fmaf(-2.0f * inter, __fdividef(1.0f, uni), c);
    c = fmaf(-2.0f * uni,   __fdividef(1.0f, ae),  c);
    return c;
}

__global__ void __launch_bounds__(TPB, 9)
cost_kernel(const float* __restrict__ pred_boxes,
            const float* __restrict__ tgt_boxes,
            float* __restrict__ out)
{
    __shared__ float  s_cls[TI * NC];   // 3.6 KB
    __shared__ float4 s_qxy[TI];
    __shared__ float4 s_qc[TI];

    const int t  = threadIdx.x;
    const int r0 = blockIdx.x * TI;
    const int j0 = blockIdx.y * TGT_PER_BLK + 2 * t;

    for (int k = t; k < TI * NC; k += TPB)
        s_cls[k] = g_cls2[r0 * NC + k];
    if (t < TI) {
        s_qxy[t] = g_qxyxy[r0 + t];
        s_qc[t]  = reinterpret_cast<const float4*>(pred_boxes)[r0 + t];
    }

    // per-thread target constants (registers; must stay resident — see R5)
    const float4 t0xy = g_txyxy[j0];
    const float4 t1xy = g_txyxy[j0 + 1];
    const float  t0a  = g_tarea[j0];
    const float  t1a  = g_tarea[j0 + 1];
    const float4 t0c  = reinterpret_cast<const float4*>(tgt_boxes)[j0];
    const float4 t1c  = reinterpret_cast<const float4*>(tgt_boxes)[j0 + 1];
    const int id0 = g_tid[j0];
    const int id1 = g_tid[j0 + 1];
    __syncthreads();

    float* orow = out + (size_t)r0 * NT + j0;

#pragma unroll
    for (int q = 0; q < TI; ++q) {
        const float4 qxy = s_qxy[q];
        const float4 qc  = s_qc[q];
        const float  qarea = qc.z * qc.w;        // hoisted once per q
        float c0 = pair_cost(qxy, qc, qarea, t0xy, t0c, t0a, s_cls[q * NC + id0]);
        float c1 = pair_cost(qxy, qc, qarea, t1xy, t1c, t1a, s_cls[q * NC + id1]);
        *reinterpret_cast<float2*>(orow + (size_t)q * NT) = make_float2(c0, c1);
    }
}

extern "C" void kernel_launch(void* const* d_in, const int* in_sizes, int n_in,
                              void* d_out, int out_size) {
    const float* logits = (const float*)d_in[0];   // [16,900,91]
    const float* pboxes = (const float*)d_in[1];   // [16,900,4]
    const float* tboxes = (const float*)d_in[2];   // [1600,4]
    const int*   ids    = (const int*)d_in[3];     // [1600] (int32 or int64 view)
    float* out = (float*)d_out;                    // [16,900,1600]

    prep_all<<<(NROWS * NC + 255) / 256, 256>>>(logits, pboxes, tboxes, ids);
    dim3 grid(NROWS / TI, NTILE_T);
    cost_kernel<<<grid, TPB>>>(pboxes, tboxes, out);
}

// round 8
// speedup vs baseline: 1.1471x; 1.0375x over previous
#include <cuda_runtime.h>

// HungarianMatcher cost matrix: C[bs,nq,nt] =
//   5*L1(cxcywh) + 2*focal_class_cost(gathered by tgt_id) - 2*GIoU(xyxy)
//
// R7 changes vs R6 (pure issue-slot cuts; kernel shown to be slot-count bound:
// R3/R4/R6 all ~39.5us regardless of pipe mix / occupancy):
//  - epilogue folded: c = base - 2*(inter*r1 + uni*r2)  (saves 2 slots/iter)
//  - TI 10 -> 20: halves per-block prologue share (class tile + target
//    constants loaded half as many times; 3600 blocks instead of 7200)

namespace {
constexpr int BS = 16, NQ = 900, NC = 91, NT = 1600;
constexpr int NROWS = BS * NQ;     // 14400
constexpr int TI = 20;             // query rows per block (14400 % 20 == 0)
constexpr int TPB = 160;           // 5 warps
constexpr int TGT_PER_BLK = 2 * TPB;       // 320
constexpr int NTILE_T = NT / TGT_PER_BLK;  // 5
}

__device__ float  g_cls2[NROWS * NC];   // 2*cost_class + 2
__device__ float4 g_qxyxy[NROWS];
__device__ float4 g_txyxy[NT];
__device__ float  g_tarea[NT];
__device__ int    g_tid[NT];

// Fused prep: class table (+2 fold) + box xyxy + target area + id decode.
// tgt_ids is int64 in the reference; jax with x64 disabled materializes
// int32. Detect: for nonneg int64 < 2^31, every odd int32 word is 0.
// All detection reads stay within the int32 buffer size.
__global__ void prep_all(const float* __restrict__ logits,
                         const float* __restrict__ pred_boxes,
                         const float* __restrict__ tgt_boxes,
                         const int*   __restrict__ ids32) {
    int i = blockIdx.x * blockDim.x + threadIdx.x;
    if (i < NROWS * NC) {
        float x = logits[i];
        float p = __fdividef(1.0f, 1.0f + __expf(-x));
        float omp = 1.0f - p;
        float pos = 0.25f * omp * omp * (-__logf(p + 1e-8f));
        float neg = 0.75f * p * p * (-__logf(omp + 1e-8f));
        g_cls2[i] = 2.0f * (pos - neg) + 2.0f;   // +2 from -2*giou's (-1) term
    }
    if (i < NROWS + NT) {
        if (i < NROWS) {
            float4 b = reinterpret_cast<const float4*>(pred_boxes)[i];
            float4 xy;
            xy.x = b.x - 0.5f * b.z; xy.y = b.y - 0.5f * b.w;
            xy.z = b.x + 0.5f * b.z; xy.w = b.y + 0.5f * b.w;
            g_qxyxy[i] = xy;
        } else {
            int j = i - NROWS;
            float4 b = reinterpret_cast<const float4*>(tgt_boxes)[j];
            float4 xy;
            xy.x = b.x - 0.5f * b.z; xy.y = b.y - 0.5f * b.w;
            xy.z = b.x + 0.5f * b.z; xy.w = b.y + 0.5f * b.w;
            g_txyxy[j] = xy;
            g_tarea[j] = b.z * b.w;
        }
    }
    if (i < NT) {
        bool is64 = true;
#pragma unroll
        for (int k = 1; k < 128; k += 2)
            is64 &= (ids32[k] == 0);
        g_tid[i] = is64 ? ids32[2 * i] : ids32[i];
    }
}

__device__ __forceinline__ float pair_cost(
    const float4 qxy, const float4 qc, const float qarea,
    const float4 txy, const float4 tc, const float tarea,
    const float cls2p)
{
    // L1 on cxcywh
    float bb = fabsf(qc.x - tc.x) + fabsf(qc.y - tc.y)
             + fabsf(qc.z - tc.z) + fabsf(qc.w - tc.w);
    // enclosing box; intersection derived from it:
    //   min(q2,t2) - max(q1,t1) = (qw + tw) - ex ; widths are qc.z/tc.z etc.
    float ex = fmaxf(qxy.z, txy.z) - fminf(qxy.x, txy.x);
    float ey = fmaxf(qxy.w, txy.w) - fminf(qxy.y, txy.y);
    float w  = fmaxf((qc.z + tc.z) - ex, 0.0f);
    float h  = fmaxf((qc.w + tc.w) - ey, 0.0f);
    float inter = w * h;
    float uni = (qarea + tarea) - inter;
    float ae  = ex * ey;
    // C = 5*bb + (2*cls+2) - 2*(inter/uni + uni/ae)
    float base = fmaf(5.0f, bb, cls2p);
    float r1 = __fdividef(1.0f, uni);
    float r2 = __fdividef(1.0f, ae);
    float g  = fmaf(inter, r1, uni * r2);
    return fmaf(-2.0f, g, base);
}

__global__ void __launch_bounds__(TPB, 9)
cost_kernel(const float* __restrict__ pred_boxes,
            const float* __restrict__ tgt_boxes,
            float* __restrict__ out)
{
    __shared__ float  s_cls[TI * NC];   // 7.3 KB
    __shared__ float4 s_qxy[TI];
    __shared__ float4 s_qc[TI];

    const int t  = threadIdx.x;
    const int r0 = blockIdx.x * TI;
    const int j0 = blockIdx.y * TGT_PER_BLK + 2 * t;

    for (int k = t; k < TI * NC; k += TPB)
        s_cls[k] = g_cls2[r0 * NC + k];
    if (t < TI) {
        s_qxy[t] = g_qxyxy[r0 + t];
        s_qc[t]  = reinterpret_cast<const float4*>(pred_boxes)[r0 + t];
    }

    // per-thread target constants (registers; must stay resident — see R5)
    const float4 t0xy = g_txyxy[j0];
    const float4 t1xy = g_txyxy[j0 + 1];
    const float  t0a  = g_tarea[j0];
    const float  t1a  = g_tarea[j0 + 1];
    const float4 t0c  = reinterpret_cast<const float4*>(tgt_boxes)[j0];
    const float4 t1c  = reinterpret_cast<const float4*>(tgt_boxes)[j0 + 1];
    const int id0 = g_tid[j0];
    const int id1 = g_tid[j0 + 1];
    __syncthreads();

    float* orow = out + (size_t)r0 * NT + j0;

#pragma unroll
    for (int q = 0; q < TI; ++q) {
        const float4 qxy = s_qxy[q];
        const float4 qc  = s_qc[q];
        const float  qarea = qc.z * qc.w;        // hoisted once per q
        float c0 = pair_cost(qxy, qc, qarea, t0xy, t0c, t0a, s_cls[q * NC + id0]);
        float c1 = pair_cost(qxy, qc, qarea, t1xy, t1c, t1a, s_cls[q * NC + id1]);
        *reinterpret_cast<float2*>(orow + (size_t)q * NT) = make_float2(c0, c1);
    }
}

extern "C" void kernel_launch(void* const* d_in, const int* in_sizes, int n_in,
                              void* d_out, int out_size) {
    const float* logits = (const float*)d_in[0];   // [16,900,91]
    const float* pboxes = (const float*)d_in[1];   // [16,900,4]
    const float* tboxes = (const float*)d_in[2];   // [1600,4]
    const int*   ids    = (const int*)d_in[3];     // [1600] (int32 or int64 view)
    float* out = (float*)d_out;                    // [16,900,1600]

    prep_all<<<(NROWS * NC + 255) / 256, 256>>>(logits, pboxes, tboxes, ids);
    dim3 grid(NROWS / TI, NTILE_T);
    cost_kernel<<<grid, TPB>>>(pboxes, tboxes, out);
}